// round 10
// baseline (speedup 1.0000x reference)
#include <cuda_runtime.h>

#define Tn 48
#define Sn 2048
#define Bn 256
#define NB 4                 // batches per block
#define NBLK (Bn / NB)       // 64 blocks

__device__ float g_delta[Bn];

typedef unsigned long long ull;

__device__ __forceinline__ ull pack2(float lo, float hi) {
    ull r; asm("mov.b64 %0,{%1,%2};" : "=l"(r) : "f"(lo), "f"(hi)); return r;
}
__device__ __forceinline__ void fma2(ull& a, ull b, ull c) {
    asm("fma.rn.f32x2 %0,%1,%2,%0;" : "+l"(a) : "l"(b), "l"(c));
}
__device__ __forceinline__ ull add2(ull a, ull b) {
    ull r; asm("add.rn.f32x2 %0,%1,%2;" : "=l"(r) : "l"(a), "l"(b)); return r;
}
__device__ __forceinline__ void unpack2(ull v, float& lo, float& hi) {
    asm("mov.b64 {%0,%1},%2;" : "=f"(lo), "=f"(hi) : "l"(v));
}

// ---------------------------------------------------------------------------
// Forward + gold fused, FOUR batches per 64-thread block.
// Per time step each thread advances state j of 4 independent batches
// back-to-back, then ONE __syncthreads covers all four double-buffer stores:
// the fixed per-step cost (barrier release + first-LDS latency + bookkeeping,
// ~120 cyc) is amortized 4x, and the independent sub-chains overlap through
// the scoreboard (batch u+1 loads issue while batch u FMAs drain).
// E = exp(transitions) is packed once in 24 f32x2 registers shared by all 4.
// Math per batch identical to R9: linear domain, exponent-only rescaling,
// 24 FFMA2 inner product, alpha_i[k] = Esum*ln2 + log(S_i[k]) exactly.
// ---------------------------------------------------------------------------
__global__ __launch_bounds__(64)
void crf_fused_kernel(const float* __restrict__ emis,
                      const int*   __restrict__ tags32,
                      const int*   __restrict__ mask,
                      const float* __restrict__ trans,
                      const float* __restrict__ startT,
                      const float* __restrict__ endT)
{
    __shared__ __align__(16) float sP[2][NB][64];
    __shared__ float  sRed[NB][64];
    __shared__ double sG[64];
    __shared__ int    sC[64];
    __shared__ int    s_is64;

    const int blk = blockIdx.x;
    const int j = threadIdx.x;
    const bool act = (j < Tn);
    const int jj = act ? j : 0;

    // int64-vs-int32 sniff for tags (odd 32-bit words all zero => int64)
    if (j < 32) {
        unsigned hw = (unsigned)tags32[2 * j + 1];
        #pragma unroll
        for (int off = 16; off > 0; off >>= 1)
            hw |= __shfl_down_sync(0xffffffffu, hw, off);
        if (j == 0) s_is64 = (hw == 0u) ? 1 : 0;
    }

    // E column packed over k-pairs (shared by all 4 batches)
    ull Epk[Tn / 2];
    #pragma unroll
    for (int p = 0; p < Tn / 2; ++p)
        Epk[p] = pack2(__expf(trans[(2 * p)     * Tn + jj]),
                       __expf(trans[(2 * p + 1) * Tn + jj]));

    const float* em_b[NB];
    const int*   mk_b[NB];
    float own[NB];
    int   Esum[NB];
    float f0[NB], f1[NB], f2[NB], f3[NB];
    int   m0[NB], m1[NB], m2[NB], m3[NB];

    #pragma unroll
    for (int u = 0; u < NB; ++u) {
        const int b = blk + u * NBLK;
        em_b[u] = emis + (size_t)b * Sn * Tn;
        mk_b[u] = mask + (size_t)b * Sn;
        own[u]  = __expf(startT[jj] + em_b[u][jj]);
        sP[0][u][j] = own[u];
        Esum[u] = 0;
        f0[u] = __expf(em_b[u][1 * Tn + jj]);
        f1[u] = __expf(em_b[u][2 * Tn + jj]);
        f2[u] = __expf(em_b[u][3 * Tn + jj]);
        f3[u] = __expf(em_b[u][4 * Tn + jj]);
        m0[u] = mk_b[u][1]; m1[u] = mk_b[u][2];
        m2[u] = mk_b[u][3]; m3[u] = mk_b[u][4];
    }

    __syncthreads();

    int cur = 0;
    #pragma unroll 4
    for (int i = 1; i < Sn; ++i) {
        const int ip = (i + 4 < Sn) ? (i + 4) : (Sn - 1);

        #pragma unroll
        for (int u = 0; u < NB; ++u) {
            const float F  = f0[u];
            const int   mi = m0[u];

            const ulonglong2* __restrict__ p2 =
                (const ulonglong2*)sP[cur][u];

            ull a0 = 0ull, a1 = 0ull, a2 = 0ull, a3 = 0ull;
            ull q00 = 0ull;
            #pragma unroll
            for (int m = 0; m < 12; m += 2) {
                const ulonglong2 qa = p2[m + 0];
                const ulonglong2 qb = p2[m + 1];
                if (m == 0) q00 = qa.x;
                fma2(a0, qa.x, Epk[2 * m + 0]);
                fma2(a1, qa.y, Epk[2 * m + 1]);
                fma2(a2, qb.x, Epk[2 * m + 2]);
                fma2(a3, qb.y, Epk[2 * m + 3]);
            }

            float q0f, q1f; unpack2(q00, q0f, q1f);
            const int  xb = __float_as_int(q0f) >> 23;
            const float r = __int_as_float((254 - xb) << 23);
            const float Fr = F * r;

            const ull s = add2(add2(a0, a1), add2(a2, a3));
            float slo, shi; unpack2(s, slo, shi);
            const float Qn = (slo + shi) * Fr;

            const float out = mi ? Qn : own[u];
            own[u] = out;
            sP[cur ^ 1][u][j] = out;
            Esum[u] += mi ? (xb - 127) : 0;

            // rotate prefetch pipeline + fetch i+4 (overlaps barrier wait)
            f0[u] = f1[u]; f1[u] = f2[u]; f2[u] = f3[u];
            m0[u] = m1[u]; m1[u] = m2[u]; m2[u] = m3[u];
            f3[u] = __expf(em_b[u][(size_t)ip * Tn + jj]);
            m3[u] = mk_b[u][ip];
        }

        cur ^= 1;
        __syncthreads();
    }

    // ---- forward finalize (per batch) ----
    #pragma unroll
    for (int u = 0; u < NB; ++u)
        sRed[u][j] = act ? sP[cur][u][j] * __expf(endT[jj]) : 0.f;

    // ---- gold (post-loop, latency-tolerant gathers), one batch at a time --
    const int is64 = s_is64;
    for (int u = 0; u < NB; ++u) {
        const int b = blk + u * NBLK;
        const size_t base = (size_t)b * Sn;
        const float* em = em_b[u];
        const int*   mk = mk_b[u];

        double gacc = 0.0;
        int cnt = 0;
        for (int i = j; i < Sn; i += 64) {
            const int m = mk[i];
            cnt += m;
            if (i >= 1 && m) {
                const size_t ic = base + (size_t)i;
                const int tp = is64 ? tags32[(ic - 1) << 1] : tags32[ic - 1];
                const int tc = is64 ? tags32[ic << 1]       : tags32[ic];
                gacc += (double)trans[tp * Tn + tc]
                      + (double)em[(size_t)i * Tn + tc];
            }
        }
        sG[j] = gacc;
        sC[j] = cnt;
        __syncthreads();
        for (int s2 = 32; s2 > 0; s2 >>= 1) {
            if (j < s2) { sG[j] += sG[j + s2]; sC[j] += sC[j + s2]; }
            __syncthreads();
        }

        if (j == 0) {
            float tot = 0.f;
            #pragma unroll
            for (int k = 0; k < Tn; ++k) tot += sRed[u][k];
            const double fwd = (double)Esum[u] * 0.6931471805599453
                             + (double)logf(tot);

            const int t0 = is64 ? tags32[base << 1] : tags32[base];
            double gold = sG[0] + (double)startT[t0] + (double)em[t0];
            const size_t il = base + (size_t)(sC[0] - 1);
            const int tl = is64 ? tags32[il << 1] : tags32[il];
            gold += (double)endT[tl];

            g_delta[b] = (float)(fwd - gold);
        }
        __syncthreads();
    }
}

// ---------------------------------------------------------------------------
// Final: out = mean(g_delta)
// ---------------------------------------------------------------------------
__global__ __launch_bounds__(256)
void crf_final_kernel(float* __restrict__ out)
{
    __shared__ double sred[256];
    const int t = threadIdx.x;
    sred[t] = (double)g_delta[t];
    __syncthreads();
    for (int s2 = 128; s2 > 0; s2 >>= 1) {
        if (t < s2) sred[t] += sred[t + s2];
        __syncthreads();
    }
    if (t == 0) out[0] = (float)(sred[0] / (double)Bn);
}

extern "C" void kernel_launch(void* const* d_in, const int* in_sizes, int n_in,
                              void* d_out, int out_size)
{
    const float* emis   = (const float*)d_in[0];
    const int*   tags32 = (const int*)d_in[1];   // int32 OR int64 viewed as words
    const int*   mask   = (const int*)d_in[2];
    const float* trans  = (const float*)d_in[3];
    const float* startT = (const float*)d_in[4];
    const float* endT   = (const float*)d_in[5];
    float* out = (float*)d_out;

    crf_fused_kernel<<<NBLK, 64>>>(emis, tags32, mask, trans, startT, endT);
    crf_final_kernel<<<1, 256>>>(out);
}

// round 11
// speedup vs baseline: 2.0403x; 2.0403x over previous
#include <cuda_runtime.h>

#define Tn 48
#define Sn 2048
#define Bn 256
#define NBLK 128             // 2 batches per block

__device__ float g_delta[Bn];

typedef unsigned long long ull;

__device__ __forceinline__ ull pack2(float lo, float hi) {
    ull r; asm("mov.b64 %0,{%1,%2};" : "=l"(r) : "f"(lo), "f"(hi)); return r;
}
__device__ __forceinline__ void fma2(ull& a, ull b, ull c) {
    asm("fma.rn.f32x2 %0,%1,%2,%0;" : "+l"(a) : "l"(b), "l"(c));
}
__device__ __forceinline__ ull add2(ull a, ull b) {
    ull r; asm("add.rn.f32x2 %0,%1,%2;" : "=l"(r) : "l"(a), "l"(b)); return r;
}
__device__ __forceinline__ void unpack2(ull v, float& lo, float& hi) {
    asm("mov.b64 {%0,%1},%2;" : "=f"(lo), "=f"(hi) : "l"(v));
}

// one batch's forward step: 12 LDS.128 + 24 FFMA2 + exponent rescale
__device__ __forceinline__ float fwd_step(const ulonglong2* __restrict__ p2,
                                          const ull* __restrict__ Epk,
                                          float F, int& xb_out)
{
    ull a0 = 0ull, a1 = 0ull, a2 = 0ull, a3 = 0ull;
    ull q00 = 0ull;
    #pragma unroll
    for (int m = 0; m < 12; m += 2) {
        const ulonglong2 qa = p2[m + 0];
        const ulonglong2 qb = p2[m + 1];
        if (m == 0) q00 = qa.x;
        fma2(a0, qa.x, Epk[2 * m + 0]);
        fma2(a1, qa.y, Epk[2 * m + 1]);
        fma2(a2, qb.x, Epk[2 * m + 2]);
        fma2(a3, qb.y, Epk[2 * m + 3]);
    }
    float q0f, q1f; unpack2(q00, q0f, q1f);
    const int  xb = __float_as_int(q0f) >> 23;
    const float r = __int_as_float((254 - xb) << 23);
    const ull s = add2(add2(a0, a1), add2(a2, a3));
    float slo, shi; unpack2(s, slo, shi);
    xb_out = xb;
    return (slo + shi) * (F * r);
}

// ---------------------------------------------------------------------------
// Forward + gold fused, TWO batches per 64-thread block, all per-batch state
// in flat scalars (R10's indexed arrays demoted to local memory -> 5x
// regression; this keeps everything register-resident by construction).
// Per step: two independent matvecs back-to-back, ONE __syncthreads covers
// both double-buffer stores -> fixed per-step cost (barrier release + first
// LDS + bookkeeping ~120cyc) amortized 2x, and batch B's loads issue while
// batch A's FMAs drain. Math per batch identical to R9 (exact exponent
// rescaling; alpha_i[k] = Esum*ln2 + log(S_i[k])).
// ---------------------------------------------------------------------------
__global__ __launch_bounds__(64)
void crf_fused_kernel(const float* __restrict__ emis,
                      const int*   __restrict__ tags32,
                      const int*   __restrict__ mask,
                      const float* __restrict__ trans,
                      const float* __restrict__ startT,
                      const float* __restrict__ endT)
{
    __shared__ __align__(16) float sP[2][2][64];   // [buf][batch][state]
    __shared__ float  sRedA[64], sRedB[64];
    __shared__ double sG[64];
    __shared__ int    sC[64];
    __shared__ int    s_is64;

    const int blk = blockIdx.x;
    const int bA = blk, bB = blk + NBLK;
    const int j = threadIdx.x;
    const bool act = (j < Tn);
    const int jj = act ? j : 0;

    // int64-vs-int32 sniff for tags (odd 32-bit words all zero => int64)
    if (j < 32) {
        unsigned hw = (unsigned)tags32[2 * j + 1];
        #pragma unroll
        for (int off = 16; off > 0; off >>= 1)
            hw |= __shfl_down_sync(0xffffffffu, hw, off);
        if (j == 0) s_is64 = (hw == 0u) ? 1 : 0;
    }

    // E column packed over k-pairs (shared by both batches)
    ull Epk[Tn / 2];
    #pragma unroll
    for (int p = 0; p < Tn / 2; ++p)
        Epk[p] = pack2(__expf(trans[(2 * p)     * Tn + jj]),
                       __expf(trans[(2 * p + 1) * Tn + jj]));

    const float* emA = emis + (size_t)bA * Sn * Tn;
    const float* emB = emis + (size_t)bB * Sn * Tn;
    const int*   mkA = mask + (size_t)bA * Sn;
    const int*   mkB = mask + (size_t)bB * Sn;

    float ownA = __expf(startT[jj] + emA[jj]);
    float ownB = __expf(startT[jj] + emB[jj]);
    sP[0][0][j] = ownA;
    sP[0][1][j] = ownB;
    int EsA = 0, EsB = 0;

    // prefetch pipelines (distance 4), flat scalars
    float fA0 = __expf(emA[1 * Tn + jj]), fB0 = __expf(emB[1 * Tn + jj]);
    float fA1 = __expf(emA[2 * Tn + jj]), fB1 = __expf(emB[2 * Tn + jj]);
    float fA2 = __expf(emA[3 * Tn + jj]), fB2 = __expf(emB[3 * Tn + jj]);
    float fA3 = __expf(emA[4 * Tn + jj]), fB3 = __expf(emB[4 * Tn + jj]);
    int mA0 = mkA[1], mA1 = mkA[2], mA2 = mkA[3], mA3 = mkA[4];
    int mB0 = mkB[1], mB1 = mkB[2], mB2 = mkB[3], mB3 = mkB[4];

    __syncthreads();

    int cur = 0;
    #pragma unroll 2
    for (int i = 1; i < Sn; ++i) {
        // batch A
        {
            int xb;
            const float Qn = fwd_step((const ulonglong2*)sP[cur][0],
                                      Epk, fA0, xb);
            const float out = mA0 ? Qn : ownA;
            ownA = out;
            sP[cur ^ 1][0][j] = out;
            EsA += mA0 ? (xb - 127) : 0;
        }
        // batch B (independent; overlaps A's FMA drain)
        {
            int xb;
            const float Qn = fwd_step((const ulonglong2*)sP[cur][1],
                                      Epk, fB0, xb);
            const float out = mB0 ? Qn : ownB;
            ownB = out;
            sP[cur ^ 1][1][j] = out;
            EsB += mB0 ? (xb - 127) : 0;
        }

        // rotate prefetch + fetch i+4 (issues before barrier, overlaps wait)
        const int ip = (i + 4 < Sn) ? (i + 4) : (Sn - 1);
        fA0 = fA1; fA1 = fA2; fA2 = fA3;
        fB0 = fB1; fB1 = fB2; fB2 = fB3;
        mA0 = mA1; mA1 = mA2; mA2 = mA3;
        mB0 = mB1; mB1 = mB2; mB2 = mB3;
        fA3 = __expf(emA[(size_t)ip * Tn + jj]);
        fB3 = __expf(emB[(size_t)ip * Tn + jj]);
        mA3 = mkA[ip];
        mB3 = mkB[ip];

        cur ^= 1;
        __syncthreads();
    }

    // ---- forward finalize ----
    const float wEnd = act ? __expf(endT[jj]) : 0.f;
    sRedA[j] = act ? sP[cur][0][j] * wEnd : 0.f;
    sRedB[j] = act ? sP[cur][1][j] * wEnd : 0.f;

    // ---- gold (post-loop), one batch at a time ----
    const int is64 = s_is64;
    #pragma unroll
    for (int u = 0; u < 2; ++u) {
        const int b = u ? bB : bA;
        const size_t base = (size_t)b * Sn;
        const float* em = u ? emB : emA;
        const int*   mk = u ? mkB : mkA;

        double gacc = 0.0;
        int cnt = 0;
        for (int i = j; i < Sn; i += 64) {
            const int m = mk[i];
            cnt += m;
            if (i >= 1 && m) {
                const size_t ic = base + (size_t)i;
                const int tp = is64 ? tags32[(ic - 1) << 1] : tags32[ic - 1];
                const int tc = is64 ? tags32[ic << 1]       : tags32[ic];
                gacc += (double)trans[tp * Tn + tc]
                      + (double)em[(size_t)i * Tn + tc];
            }
        }
        __syncthreads();
        sG[j] = gacc;
        sC[j] = cnt;
        __syncthreads();
        for (int s2 = 32; s2 > 0; s2 >>= 1) {
            if (j < s2) { sG[j] += sG[j + s2]; sC[j] += sC[j + s2]; }
            __syncthreads();
        }

        if (j == 0) {
            const float* sR = u ? sRedB : sRedA;
            float tot = 0.f;
            #pragma unroll
            for (int k = 0; k < Tn; ++k) tot += sR[k];
            const double fwd = (double)(u ? EsB : EsA) * 0.6931471805599453
                             + (double)logf(tot);

            const int t0 = is64 ? tags32[base << 1] : tags32[base];
            double gold = sG[0] + (double)startT[t0] + (double)em[t0];
            const size_t il = base + (size_t)(sC[0] - 1);
            const int tl = is64 ? tags32[il << 1] : tags32[il];
            gold += (double)endT[tl];

            g_delta[b] = (float)(fwd - gold);
        }
    }
}

// ---------------------------------------------------------------------------
// Final: out = mean(g_delta)
// ---------------------------------------------------------------------------
__global__ __launch_bounds__(256)
void crf_final_kernel(float* __restrict__ out)
{
    __shared__ double sred[256];
    const int t = threadIdx.x;
    sred[t] = (double)g_delta[t];
    __syncthreads();
    for (int s2 = 128; s2 > 0; s2 >>= 1) {
        if (t < s2) sred[t] += sred[t + s2];
        __syncthreads();
    }
    if (t == 0) out[0] = (float)(sred[0] / (double)Bn);
}

extern "C" void kernel_launch(void* const* d_in, const int* in_sizes, int n_in,
                              void* d_out, int out_size)
{
    const float* emis   = (const float*)d_in[0];
    const int*   tags32 = (const int*)d_in[1];   // int32 OR int64 viewed as words
    const int*   mask   = (const int*)d_in[2];
    const float* trans  = (const float*)d_in[3];
    const float* startT = (const float*)d_in[4];
    const float* endT   = (const float*)d_in[5];
    float* out = (float*)d_out;

    crf_fused_kernel<<<NBLK, 64>>>(emis, tags32, mask, trans, startT, endT);
    crf_final_kernel<<<1, 256>>>(out);
}

// round 12
// speedup vs baseline: 4.4825x; 2.1970x over previous
#include <cuda_runtime.h>

#define Tn 48
#define Sn 2048
#define Bn 256

__device__ float g_delta[Bn];

typedef unsigned long long ull;

__device__ __forceinline__ ull pack2(float lo, float hi) {
    ull r; asm("mov.b64 %0,{%1,%2};" : "=l"(r) : "f"(lo), "f"(hi)); return r;
}
__device__ __forceinline__ void fma2(ull& a, ull b, ull c) {
    asm("fma.rn.f32x2 %0,%1,%2,%0;" : "+l"(a) : "l"(b), "l"(c));
}
__device__ __forceinline__ ull add2(ull a, ull b) {
    ull r; asm("add.rn.f32x2 %0,%1,%2;" : "=l"(r) : "l"(a), "l"(b)); return r;
}
__device__ __forceinline__ void unpack2(ull v, float& lo, float& hi) {
    asm("mov.b64 {%0,%1},%2;" : "=f"(lo), "=f"(hi) : "l"(v));
}

// ---------------------------------------------------------------------------
// R9 design (proven optimum: 1 batch / 64 threads / one matvec per warp-step):
// linear-domain forward, exponent-only rescaling, 24 FFMA2 inner product,
// alpha double-buffered in shared as plain float[64] read via C++ ulonglong2,
// own-value register-carried, normalizer folded into the first vector load,
// prefetch issued between STS and barrier, gold fused post-loop.
// R12 delta: time loop unrolled x4 so the prefetch-pipeline rotation becomes
// register renaming and the double-buffer addresses fold to immediates.
// Invariant: alpha_i[k] = Esum*ln2 + log(S_i[k]) (exact integer exponent).
// ---------------------------------------------------------------------------
__global__ __launch_bounds__(64)
void crf_fused_kernel(const float* __restrict__ emis,
                      const int*   __restrict__ tags32,
                      const int*   __restrict__ mask,
                      const float* __restrict__ trans,
                      const float* __restrict__ startT,
                      const float* __restrict__ endT)
{
    __shared__ __align__(16) float sP[2][64];
    __shared__ float  sRed[64];
    __shared__ double sG[64];
    __shared__ int    sC[64];
    __shared__ int    s_is64;

    const int b = blockIdx.x;
    const int j = threadIdx.x;
    const bool act = (j < Tn);
    const int jj = act ? j : 0;

    // int64-vs-int32 sniff for tags (odd 32-bit words all zero => int64)
    if (j < 32) {
        unsigned hw = (unsigned)tags32[2 * j + 1];
        #pragma unroll
        for (int off = 16; off > 0; off >>= 1)
            hw |= __shfl_down_sync(0xffffffffu, hw, off);
        if (j == 0) s_is64 = (hw == 0u) ? 1 : 0;
    }

    // E column packed over k-pairs
    ull Epk[Tn / 2];
    #pragma unroll
    for (int p = 0; p < Tn / 2; ++p)
        Epk[p] = pack2(__expf(trans[(2 * p)     * Tn + jj]),
                       __expf(trans[(2 * p + 1) * Tn + jj]));

    const float* em_b = emis + (size_t)b * Sn * Tn;
    const int*   mk_b = mask + (size_t)b * Sn;

    // init
    float own = __expf(startT[jj] + em_b[jj]);   // alpha_0[j], register-carried
    sP[0][j] = own;
    int Esum = 0;

    // prefetch pipeline (distance 4)
    float f0 = __expf(em_b[1 * Tn + jj]);
    float f1 = __expf(em_b[2 * Tn + jj]);
    float f2 = __expf(em_b[3 * Tn + jj]);
    float f3 = __expf(em_b[4 * Tn + jj]);
    int   m0 = mk_b[1], m1 = mk_b[2], m2 = mk_b[3], m3 = mk_b[4];

    __syncthreads();

    int cur = 0;
    #pragma unroll 4
    for (int i = 1; i < Sn; ++i) {
        const float F  = f0;
        const int   mi = m0;

        const ulonglong2* __restrict__ p2 = (const ulonglong2*)sP[cur];

        ull a0 = 0ull, a1 = 0ull, a2 = 0ull, a3 = 0ull;
        ull q00 = 0ull;
        #pragma unroll
        for (int m = 0; m < 12; m += 2) {
            const ulonglong2 qa = p2[m + 0];
            const ulonglong2 qb = p2[m + 1];
            if (m == 0) q00 = qa.x;            // (alpha0, alpha1)
            fma2(a0, qa.x, Epk[2 * m + 0]);
            fma2(a1, qa.y, Epk[2 * m + 1]);
            fma2(a2, qb.x, Epk[2 * m + 2]);
            fma2(a3, qb.y, Epk[2 * m + 3]);
        }

        // normalizer from exponent of alpha[0] (lo half of q00): exact
        float q0f, q1f; unpack2(q00, q0f, q1f);
        const int  xb = __float_as_int(q0f) >> 23;
        const float r = __int_as_float((254 - xb) << 23);
        const float Fr = F * r;

        const ull s = add2(add2(a0, a1), add2(a2, a3));
        float slo, shi; unpack2(s, slo, shi);
        const float Qn = (slo + shi) * Fr;

        const float out = mi ? Qn : own;       // register select, no LDS
        own = out;
        const int nxt = cur ^ 1;
        sP[nxt][j] = out;
        Esum += mi ? (xb - 127) : 0;

        // prefetch for i+4 (issues before the barrier -> overlaps the wait;
        // rotation is register renaming under unroll 4)
        f0 = f1; f1 = f2; f2 = f3;
        m0 = m1; m1 = m2; m2 = m3;
        const int ip = (i + 4 < Sn) ? (i + 4) : (Sn - 1);
        f3 = __expf(em_b[(size_t)ip * Tn + jj]);
        m3 = mk_b[ip];

        cur = nxt;
        __syncthreads();
    }

    // ---- forward finalize ----
    sRed[j] = act ? sP[cur][j] * __expf(endT[jj]) : 0.f;

    // ---- gold (post-loop, latency-tolerant gathers) ----
    const int is64 = s_is64;
    const size_t base = (size_t)b * Sn;
    double gacc = 0.0;
    int cnt = 0;
    for (int i = j; i < Sn; i += 64) {
        const int m = mk_b[i];
        cnt += m;
        if (i >= 1 && m) {
            const size_t ic = base + (size_t)i;
            const int tp = is64 ? tags32[(ic - 1) << 1] : tags32[ic - 1];
            const int tc = is64 ? tags32[ic << 1]       : tags32[ic];
            gacc += (double)trans[tp * Tn + tc]
                  + (double)em_b[(size_t)i * Tn + tc];
        }
    }
    sG[j] = gacc;
    sC[j] = cnt;
    __syncthreads();
    for (int s2 = 32; s2 > 0; s2 >>= 1) {
        if (j < s2) { sG[j] += sG[j + s2]; sC[j] += sC[j + s2]; }
        __syncthreads();
    }

    if (j == 0) {
        float tot = 0.f;
        #pragma unroll
        for (int k = 0; k < Tn; ++k) tot += sRed[k];
        const double fwd = (double)Esum * 0.6931471805599453
                         + (double)logf(tot);

        const int t0 = is64 ? tags32[base << 1] : tags32[base];
        double gold = sG[0] + (double)startT[t0] + (double)em_b[t0];
        const size_t il = base + (size_t)(sC[0] - 1);
        const int tl = is64 ? tags32[il << 1] : tags32[il];
        gold += (double)endT[tl];

        g_delta[b] = (float)(fwd - gold);
    }
}

// ---------------------------------------------------------------------------
// Final: out = mean(g_delta)
// ---------------------------------------------------------------------------
__global__ __launch_bounds__(256)
void crf_final_kernel(float* __restrict__ out)
{
    __shared__ double sred[256];
    const int t = threadIdx.x;
    sred[t] = (double)g_delta[t];
    __syncthreads();
    for (int s2 = 128; s2 > 0; s2 >>= 1) {
        if (t < s2) sred[t] += sred[t + s2];
        __syncthreads();
    }
    if (t == 0) out[0] = (float)(sred[0] / (double)Bn);
}

extern "C" void kernel_launch(void* const* d_in, const int* in_sizes, int n_in,
                              void* d_out, int out_size)
{
    const float* emis   = (const float*)d_in[0];
    const int*   tags32 = (const int*)d_in[1];   // int32 OR int64 viewed as words
    const int*   mask   = (const int*)d_in[2];
    const float* trans  = (const float*)d_in[3];
    const float* startT = (const float*)d_in[4];
    const float* endT   = (const float*)d_in[5];
    float* out = (float*)d_out;

    crf_fused_kernel<<<Bn, 64>>>(emis, tags32, mask, trans, startT, endT);
    crf_final_kernel<<<1, 256>>>(out);
}